// round 4
// baseline (speedup 1.0000x reference)
#include <cuda_runtime.h>
#include <math.h>

#define NUM_FIELDS 32
#define FIELD_DIM  50000
#define EMB_DIM    64
#define ATT_DIM    32
#define NPAIRS     496
#define ET_STRIDE  33   // padded stride: bank = (d + f) % 32 -> conflict-free / broadcast

typedef unsigned long long ull;

// ---- packed f32x2 helpers (PTX-only; ptxas never auto-fuses to FFMA2) ----
__device__ __forceinline__ ull pk2(float lo, float hi){
    ull r; asm("mov.b64 %0, {%1, %2};" : "=l"(r) : "f"(lo), "f"(hi)); return r;
}
__device__ __forceinline__ void upk2(ull v, float &lo, float &hi){
    asm("mov.b64 {%0, %1}, %2;" : "=f"(lo), "=f"(hi) : "l"(v));
}
__device__ __forceinline__ void fma2(ull &d, ull a, ull b){
    asm("fma.rn.f32x2 %0, %1, %2, %0;" : "+l"(d) : "l"(a), "l"(b));
}

__global__ __launch_bounds__(256, 2)
void afm_kernel(const int*   __restrict__ x,
                const float* __restrict__ emb,
                const float* __restrict__ lin,
                const float* __restrict__ lin_bias,
                const float* __restrict__ W1,
                const float* __restrict__ b1,
                const float* __restrict__ w2,
                const float* __restrict__ pw,
                float*       __restrict__ out)
{
    __shared__ float sEt[EMB_DIM * ET_STRIDE];          // transposed embeddings Et[d][f]
    __shared__ __align__(16) float sW1[EMB_DIM * ATT_DIM]; // row-major [d][a]
    __shared__ float sB1[ATT_DIM], sW2[ATT_DIM], sPW[EMB_DIM];
    __shared__ float sS[512], sQ[512];
    __shared__ float sRed[256], sRedB[256];
    __shared__ float sFirst;

    const int t = threadIdx.x;
    const int b = blockIdx.x;

    // ---- gather embeddings -> transposed SMEM (conflict-free scatter) ----
    {
        int f = t >> 3, k = t & 7;
        int id = x[b * NUM_FIELDS + f] + f * FIELD_DIM;
        const float4* src = (const float4*)(emb + (size_t)id * EMB_DIM + k * 8);
        float4 v0 = src[0], v1 = src[1];
        int d0 = k * 8;
        sEt[(d0+0)*ET_STRIDE+f] = v0.x; sEt[(d0+1)*ET_STRIDE+f] = v0.y;
        sEt[(d0+2)*ET_STRIDE+f] = v0.z; sEt[(d0+3)*ET_STRIDE+f] = v0.w;
        sEt[(d0+4)*ET_STRIDE+f] = v1.x; sEt[(d0+5)*ET_STRIDE+f] = v1.y;
        sEt[(d0+6)*ET_STRIDE+f] = v1.z; sEt[(d0+7)*ET_STRIDE+f] = v1.w;
    }
    // ---- stage small weights ----
    {
        const float4* g = (const float4*)W1;
        float4* s4 = (float4*)sW1;
        s4[t]       = g[t];
        s4[t + 256] = g[t + 256];
    }
    if (t < 32) { sB1[t] = b1[t]; sW2[t] = w2[t]; }
    if (t < 64) sPW[t] = pw[t];
    if (t >= 240) { sS[t + 256] = -1e30f; sQ[t + 256] = 0.f; }   // pad slots 496..511

    // ---- first-order linear term (warp 0) ----
    if (t < 32) {
        int id = x[b * NUM_FIELDS + t] + t * FIELD_DIM;
        float v = lin[id];
        #pragma unroll
        for (int off = 16; off; off >>= 1) v += __shfl_down_sync(0xffffffffu, v, off);
        if (t == 0) sFirst = v + lin_bias[0];
    }
    __syncthreads();

    // ---- decode pair indices (triu order, row-major i<j) ----
    const int pA = t;
    const int pB = t + 256;
    const bool hasB = (pB < NPAIRS);
    int ia, ja, ib, jb;
    {
        int p = pA, i = 0, c = 31;
        while (p >= c) { p -= c; c--; i++; }
        ia = i; ja = i + 1 + p;
    }
    if (hasB) {
        int p = pB, i = 0, c = 31;
        while (p >= c) { p -= c; c--; i++; }
        ib = i; jb = i + 1 + p;
    } else { ib = 0; jb = 1; }

    // ---- per-pair bilinear forms: h[a] = sum_d e_i*e_j*W1[d][a], q = sum_d e_i*e_j*pw[d]
    ull h0[16], h1[16];
    #pragma unroll
    for (int k = 0; k < 16; k++) { h0[k] = 0ull; h1[k] = 0ull; }
    float q0 = 0.f, q1 = 0.f;

    const float* pe  = sEt;
    const ull*   pwr = (const ull*)sW1;   // pairs (a=2k, a=2k+1)
    const float* ppw = sPW;
    #pragma unroll 2
    for (int d = 0; d < EMB_DIM; d++) {
        float pa = pe[ia] * pe[ja];       // bank (d+i)%32: distinct-i -> distinct banks, same-i -> broadcast
        float pb = pe[ib] * pe[jb];
        float pwd = *ppw;
        q0 = fmaf(pa, pwd, q0);
        q1 = fmaf(pb, pwd, q1);
        ull pa2 = pk2(pa, pa), pb2 = pk2(pb, pb);
        #pragma unroll
        for (int k = 0; k < 16; k++) {
            ull wk = pwr[k];              // 64-bit broadcast load
            fma2(h0[k], wk, pa2);
            fma2(h1[k], wk, pb2);
        }
        pe += ET_STRIDE; pwr += 16; ppw++;
    }

    // ---- attention MLP head: s = sum_a w2[a]*relu(h[a]+b1[a]) ----
    float s0 = 0.f, s1 = 0.f;
    #pragma unroll
    for (int k = 0; k < 16; k++) {
        float lo, hi;
        upk2(h0[k], lo, hi);
        s0 += sW2[2*k]   * fmaxf(lo + sB1[2*k],   0.f)
            + sW2[2*k+1] * fmaxf(hi + sB1[2*k+1], 0.f);
        upk2(h1[k], lo, hi);
        s1 += sW2[2*k]   * fmaxf(lo + sB1[2*k],   0.f)
            + sW2[2*k+1] * fmaxf(hi + sB1[2*k+1], 0.f);
    }
    sS[pA] = s0; sQ[pA] = q0;
    if (hasB) { sS[pB] = s1; sQ[pB] = q1; }
    __syncthreads();

    // ---- softmax over 496 pairs + weighted sum of q (block reductions) ----
    float m = fmaxf(sS[t], sS[t + 256]);
    sRed[t] = m; __syncthreads();
    #pragma unroll
    for (int off = 128; off > 0; off >>= 1) {
        if (t < off) sRed[t] = fmaxf(sRed[t], sRed[t + off]);
        __syncthreads();
    }
    float mx = sRed[0];
    __syncthreads();

    float e0 = expf(sS[t] - mx);
    float e1 = (t < 240) ? expf(sS[t + 256] - mx) : 0.f;
    sRed[t]  = e0 + e1;
    sRedB[t] = e0 * sQ[t] + e1 * sQ[t + 256];
    __syncthreads();
    #pragma unroll
    for (int off = 128; off > 0; off >>= 1) {
        if (t < off) { sRed[t] += sRed[t + off]; sRedB[t] += sRedB[t + off]; }
        __syncthreads();
    }

    if (t == 0) {
        float second = sRedB[0] / sRed[0];   // sum(attn * q)
        float y = sFirst + second;
        out[b] = 1.f / (1.f + expf(-y));
    }
}

extern "C" void kernel_launch(void* const* d_in, const int* in_sizes, int n_in,
                              void* d_out, int out_size)
{
    const int*   x   = (const int*)  d_in[0];
    const float* emb = (const float*)d_in[1];
    const float* lin = (const float*)d_in[2];
    const float* lb  = (const float*)d_in[3];
    const float* W1  = (const float*)d_in[4];
    const float* b1  = (const float*)d_in[5];
    const float* w2  = (const float*)d_in[6];
    const float* pwv = (const float*)d_in[7];
    const int B = in_sizes[0] / NUM_FIELDS;
    afm_kernel<<<B, 256>>>(x, emb, lin, lb, W1, b1, w2, pwv, (float*)d_out);
}

// round 6
// speedup vs baseline: 2.1576x; 2.1576x over previous
#include <cuda_runtime.h>
#include <cuda_bf16.h>
#include <math.h>
#include <stdint.h>

#define NUM_FIELDS 32
#define FIELD_DIM  50000
#define EMB_DIM    64
#define ATT_DIM    32
#define NPAIRS     496
#define ET_STRIDE  33
#define GRID_CTAS  296

// ---- dynamic smem layout (bytes) ----
#define OFF_FIRST  0
#define OFF_B1     16      // 32 f32
#define OFF_W2     144     // 32 f32
#define OFF_PW     272     // 64 f32
#define OFF_S      528     // 512 f32
#define OFF_Q      2576    // 512 f32
#define OFF_RED    4624    // 256 f32
#define OFF_REDB   5648    // 256 f32
#define OFF_ET     6672    // 64*33 f32 = 8448 B
#define OFF_P      15360   // 512 rows x 128 B bf16 = 65536 (128B-aligned, XOR-swizzled)
#define SMEM_TOTAL 80896

__device__ __forceinline__ uint32_t s2u(const void* p){
    uint32_t a; asm("{ .reg .u64 t; cvta.to.shared.u64 t, %1; cvt.u32.u64 %0, t; }":"=r"(a):"l"(p)); return a;
}
// pack two f32 -> bf16x2 (lo = first arg, hi = second)
__device__ __forceinline__ uint32_t bfpair(float lo, float hi){
    uint32_t r; asm("cvt.rn.bf16x2.f32 %0, %1, %2;":"=r"(r):"f"(hi),"f"(lo)); return r;
}
__device__ __forceinline__ void sts128(uint32_t addr, uint32_t a, uint32_t b, uint32_t c, uint32_t d){
    asm volatile("st.shared.v4.b32 [%0], {%1,%2,%3,%4};"::"r"(addr),"r"(a),"r"(b),"r"(c),"r"(d):"memory");
}
__device__ __forceinline__ void ldmatrix_x4(uint32_t &a0, uint32_t &a1, uint32_t &a2, uint32_t &a3, uint32_t addr){
    asm volatile("ldmatrix.sync.aligned.m8n8.x4.shared.b16 {%0,%1,%2,%3}, [%4];"
                 : "=r"(a0),"=r"(a1),"=r"(a2),"=r"(a3) : "r"(addr));
}
__device__ __forceinline__ void mma16816(float* c, uint32_t a0, uint32_t a1, uint32_t a2, uint32_t a3,
                                         uint32_t b0, uint32_t b1){
    asm volatile("mma.sync.aligned.m16n8k16.row.col.f32.bf16.bf16.f32 "
                 "{%0,%1,%2,%3}, {%4,%5,%6,%7}, {%8,%9}, {%0,%1,%2,%3};"
                 : "+f"(c[0]),"+f"(c[1]),"+f"(c[2]),"+f"(c[3])
                 : "r"(a0),"r"(a1),"r"(a2),"r"(a3),"r"(b0),"r"(b1));
}

// build one P row (pair p) into bf16 smem tile + return fp32 q_p
__device__ __forceinline__ float build_row(const float* sEt, const float* sPW,
                                           uint32_t pbase, int i, int j, int p)
{
    uint32_t rowbase = pbase + (uint32_t)p * 128;
    uint32_t xr = ((uint32_t)(p & 7)) << 4;
    const float* ei = sEt + i;
    const float* ej = sEt + j;
    float q = 0.f;
    #pragma unroll
    for (int c = 0; c < 8; c++) {
        float pr[8];
        #pragma unroll
        for (int u = 0; u < 8; u++) {
            int d = c * 8 + u;
            float v = ei[d * ET_STRIDE] * ej[d * ET_STRIDE];
            pr[u] = v;
            q = fmaf(v, sPW[d], q);
        }
        uint32_t w0 = bfpair(pr[0], pr[1]);
        uint32_t w1 = bfpair(pr[2], pr[3]);
        uint32_t w2 = bfpair(pr[4], pr[5]);
        uint32_t w3 = bfpair(pr[6], pr[7]);
        sts128(rowbase + (((uint32_t)(c * 16)) ^ xr), w0, w1, w2, w3);
    }
    return q;
}

__global__ __launch_bounds__(256, 2)
void afm_mma_kernel(const int*   __restrict__ x,
                    const float* __restrict__ emb,
                    const float* __restrict__ lin,
                    const float* __restrict__ lin_bias,
                    const float* __restrict__ W1,
                    const float* __restrict__ b1,
                    const float* __restrict__ w2,
                    const float* __restrict__ pw,
                    float*       __restrict__ out,
                    int BATCH)
{
    extern __shared__ char smem[];
    const uint32_t sb = s2u(smem);
    const int t    = threadIdx.x;
    const int wid  = t >> 5;
    const int lane = t & 31;

    float* sB1   = (float*)(smem + OFF_B1);
    float* sW2   = (float*)(smem + OFF_W2);
    float* sPW   = (float*)(smem + OFF_PW);
    float* sS    = (float*)(smem + OFF_S);
    float* sQ    = (float*)(smem + OFF_Q);
    float* sRed  = (float*)(smem + OFF_RED);
    float* sRedB = (float*)(smem + OFF_REDB);
    float* sEt   = (float*)(smem + OFF_ET);
    float* sFirst= (float*)(smem + OFF_FIRST);

    // ---- one-time init ----
    if (t < 32) { sB1[t] = b1[t]; sW2[t] = w2[t]; }
    if (t < 64) sPW[t] = pw[t];
    if (t >= 240) { sS[t + 256] = -1e30f; sQ[t + 256] = 0.f; }   // softmax pads (persist)
    // zero P pad rows 496..511 (16 rows x 128 B); never rewritten
    for (int e = t; e < 512; e += 256)
        *(uint32_t*)(smem + OFF_P + 496 * 128 + e * 4) = 0u;

    // ---- W1 as permanent B-fragments (m16n8k16, col-major B) ----
    // lane: n = nt*8 + lane/4 ; k = ks*16 + (lane%4)*2 (+8 for reg1)
    uint32_t bfrag[4][4][2];
    {
        int n  = (lane >> 2);
        int kk = (lane & 3) * 2;
        #pragma unroll
        for (int nt = 0; nt < 4; nt++) {
            #pragma unroll
            for (int ks = 0; ks < 4; ks++) {
                int k = ks * 16 + kk;
                int col = nt * 8 + n;
                bfrag[nt][ks][0] = bfpair(W1[(k    ) * 32 + col], W1[(k + 1) * 32 + col]);
                bfrag[nt][ks][1] = bfpair(W1[(k + 8) * 32 + col], W1[(k + 9) * 32 + col]);
            }
        }
    }
    // per-thread b1/w2 at this thread's C-fragment columns
    float b1r[4][2], w2r[4][2];
    {
        int c0 = (lane & 3) * 2;
        #pragma unroll
        for (int nt = 0; nt < 4; nt++) {
            b1r[nt][0] = b1[nt * 8 + c0];     b1r[nt][1] = b1[nt * 8 + c0 + 1];
            w2r[nt][0] = w2[nt * 8 + c0];     w2r[nt][1] = w2[nt * 8 + c0 + 1];
        }
    }
    __syncthreads();

    const float lbias = lin_bias[0];
    const uint32_t pbase = sb + OFF_P;

    // pair decode (triu order, i<j)
    int ia, ja, ib, jb;
    { int p = t, i = 0, c = 31; while (p >= c) { p -= c; c--; i++; } ia = i; ja = i + 1 + p; }
    const bool hasB = (t < NPAIRS - 256);
    { int p = t + 256, i = 0, c = 31; if (hasB) { while (p >= c) { p -= c; c--; i++; } ib = i; jb = i + 1 + p; } else { ib = 0; jb = 1; } }

    const int wbase = wid * 64;

    for (int b = blockIdx.x; b < BATCH; b += gridDim.x) {
        // ---- gather embeddings -> transposed fp32 SMEM ----
        {
            int f = t >> 3, k = t & 7;
            int id = x[b * NUM_FIELDS + f] + f * FIELD_DIM;
            const float4* src = (const float4*)(emb + (size_t)id * EMB_DIM + k * 8);
            float4 v0 = src[0], v1 = src[1];
            int d0 = k * 8;
            sEt[(d0+0)*ET_STRIDE+f] = v0.x; sEt[(d0+1)*ET_STRIDE+f] = v0.y;
            sEt[(d0+2)*ET_STRIDE+f] = v0.z; sEt[(d0+3)*ET_STRIDE+f] = v0.w;
            sEt[(d0+4)*ET_STRIDE+f] = v1.x; sEt[(d0+5)*ET_STRIDE+f] = v1.y;
            sEt[(d0+6)*ET_STRIDE+f] = v1.z; sEt[(d0+7)*ET_STRIDE+f] = v1.w;
        }
        if (t < 32) {   // first-order linear term
            int id = x[b * NUM_FIELDS + t] + t * FIELD_DIM;
            float v = lin[id];
            #pragma unroll
            for (int off = 16; off; off >>= 1) v += __shfl_down_sync(0xffffffffu, v, off);
            if (t == 0) *sFirst = v + lbias;
        }
        __syncthreads();

        // ---- build bf16 P rows + fp32 q ----
        sQ[t] = build_row(sEt, sPW, pbase, ia, ja, t);
        if (hasB) sQ[t + 256] = build_row(sEt, sPW, pbase, ib, jb, t + 256);
        __syncthreads();

        // ---- per-warp GEMM: 64 pair-rows x 32 a, K=64, via mma.sync bf16 ----
        #pragma unroll
        for (int half = 0; half < 2; half++) {
            float acc[2][4][4];
            #pragma unroll
            for (int m = 0; m < 2; m++)
                #pragma unroll
                for (int nt = 0; nt < 4; nt++)
                    #pragma unroll
                    for (int v = 0; v < 4; v++) acc[m][nt][v] = 0.f;

            #pragma unroll
            for (int ks = 0; ks < 4; ks++) {
                #pragma unroll
                for (int mt = 0; mt < 2; mt++) {
                    int row  = wbase + half * 32 + mt * 16 + ((lane >> 3) & 1) * 8 + (lane & 7);
                    int ch   = ks * 2 + (lane >> 4);
                    uint32_t addr = pbase + (((uint32_t)(row * 128 + ch * 16)) ^ (((uint32_t)(row & 7)) << 4));
                    uint32_t a0, a1, a2, a3;
                    ldmatrix_x4(a0, a1, a2, a3, addr);
                    #pragma unroll
                    for (int nt = 0; nt < 4; nt++)
                        mma16816(acc[mt][nt], a0, a1, a2, a3, bfrag[nt][ks][0], bfrag[nt][ks][1]);
                }
            }

            // epilogue: relu + w2 dot + quad reduce -> scores
            #pragma unroll
            for (int mt = 0; mt < 2; mt++) {
                #pragma unroll
                for (int rh = 0; rh < 2; rh++) {
                    float sp = 0.f;
                    #pragma unroll
                    for (int nt = 0; nt < 4; nt++) {
                        float v0 = acc[mt][nt][rh * 2 + 0];
                        float v1 = acc[mt][nt][rh * 2 + 1];
                        sp = fmaf(w2r[nt][0], fmaxf(v0 + b1r[nt][0], 0.f), sp);
                        sp = fmaf(w2r[nt][1], fmaxf(v1 + b1r[nt][1], 0.f), sp);
                    }
                    sp += __shfl_xor_sync(0xffffffffu, sp, 1);
                    sp += __shfl_xor_sync(0xffffffffu, sp, 2);
                    int pair = wbase + half * 32 + mt * 16 + rh * 8 + (lane >> 2);
                    if ((lane & 3) == 0 && pair < NPAIRS) sS[pair] = sp;
                }
            }
        }
        __syncthreads();

        // ---- softmax over 496 + attn-weighted sum of q ----
        sRed[t] = fmaxf(sS[t], sS[t + 256]);
        __syncthreads();
        #pragma unroll
        for (int off = 128; off > 0; off >>= 1) {
            if (t < off) sRed[t] = fmaxf(sRed[t], sRed[t + off]);
            __syncthreads();
        }
        float mx = sRed[0];
        __syncthreads();

        float e0 = expf(sS[t] - mx);
        float e1 = (t < 240) ? expf(sS[t + 256] - mx) : 0.f;
        sRed[t]  = e0 + e1;
        sRedB[t] = e0 * sQ[t] + e1 * sQ[t + 256];
        __syncthreads();
        #pragma unroll
        for (int off = 128; off > 0; off >>= 1) {
            if (t < off) { sRed[t] += sRed[t + off]; sRedB[t] += sRedB[t + off]; }
            __syncthreads();
        }
        if (t == 0) {
            float y = *sFirst + sRedB[0] / sRed[0];
            out[b] = 1.f / (1.f + expf(-y));
        }
        __syncthreads();
    }
}

extern "C" void kernel_launch(void* const* d_in, const int* in_sizes, int n_in,
                              void* d_out, int out_size)
{
    const int*   x   = (const int*)  d_in[0];
    const float* emb = (const float*)d_in[1];
    const float* lin = (const float*)d_in[2];
    const float* lb  = (const float*)d_in[3];
    const float* W1  = (const float*)d_in[4];
    const float* b1  = (const float*)d_in[5];
    const float* w2  = (const float*)d_in[6];
    const float* pwv = (const float*)d_in[7];
    const int B = in_sizes[0] / NUM_FIELDS;

    cudaFuncSetAttribute(afm_mma_kernel, cudaFuncAttributeMaxDynamicSharedMemorySize, SMEM_TOTAL);
    int grid = GRID_CTAS < B ? GRID_CTAS : B;
    afm_mma_kernel<<<grid, 256, SMEM_TOTAL>>>(x, emb, lin, lb, W1, b1, w2, pwv, (float*)d_out, B);
}

// round 7
// speedup vs baseline: 3.0643x; 1.4203x over previous
#include <cuda_runtime.h>
#include <cuda_bf16.h>
#include <math.h>
#include <stdint.h>

#define NUM_FIELDS 32
#define FIELD_DIM  50000
#define EMB_DIM    64
#define ATT_DIM    32
#define NPAIRS     496
#define GRID_CTAS  296

// ---- dynamic smem layout (bytes) ----
#define OFF_FIRST  0
#define OFF_S      16      // 512 f32
#define OFF_Q      2064    // 512 f32
#define OFF_RED    4112    // 16 f32 (warp max partials + warp sum partials)
#define OFF_REDB   4176    // 8 f32
#define OFF_ET     4224    // 32*33 u32 (bf16x2-packed Et) = 4224 B
#define OFF_P      9216    // 1024-aligned; 512 rows x 128 B bf16 = 65536
#define SMEM_TOTAL 74752

__device__ __forceinline__ uint32_t s2u(const void* p){
    uint32_t a; asm("{ .reg .u64 t; cvta.to.shared.u64 t, %1; cvt.u32.u64 %0, t; }":"=r"(a):"l"(p)); return a;
}
// pack two f32 -> bf16x2 (first arg = low half)
__device__ __forceinline__ uint32_t bfpair(float lo, float hi){
    uint32_t r; asm("cvt.rn.bf16x2.f32 %0, %1, %2;":"=r"(r):"f"(hi),"f"(lo)); return r;
}
__device__ __forceinline__ uint32_t mulbf2(uint32_t a, uint32_t b){
    uint32_t r; asm("mul.bf16x2 %0, %1, %2;":"=r"(r):"r"(a),"r"(b)); return r;
}
__device__ __forceinline__ void sts128(uint32_t addr, uint32_t a, uint32_t b, uint32_t c, uint32_t d){
    asm volatile("st.shared.v4.b32 [%0], {%1,%2,%3,%4};"::"r"(addr),"r"(a),"r"(b),"r"(c),"r"(d):"memory");
}
__device__ __forceinline__ void ldmatrix_x4(uint32_t &a0, uint32_t &a1, uint32_t &a2, uint32_t &a3, uint32_t addr){
    asm volatile("ldmatrix.sync.aligned.m8n8.x4.shared.b16 {%0,%1,%2,%3}, [%4];"
                 : "=r"(a0),"=r"(a1),"=r"(a2),"=r"(a3) : "r"(addr));
}
__device__ __forceinline__ void mma16816(float* c, uint32_t a0, uint32_t a1, uint32_t a2, uint32_t a3,
                                         uint32_t b0, uint32_t b1){
    asm volatile("mma.sync.aligned.m16n8k16.row.col.f32.bf16.bf16.f32 "
                 "{%0,%1,%2,%3}, {%4,%5,%6,%7}, {%8,%9}, {%0,%1,%2,%3};"
                 : "+f"(c[0]),"+f"(c[1]),"+f"(c[2]),"+f"(c[3])
                 : "r"(a0),"r"(a1),"r"(a2),"r"(a3),"r"(b0),"r"(b1));
}

// build one P row (pair p): bf16x2 products straight into the swizzled A tile
__device__ __forceinline__ void build_row(const uint32_t* sEt2, uint32_t pbase, int i, int j, int p)
{
    uint32_t rowbase = pbase + (uint32_t)p * 128;
    uint32_t xr = ((uint32_t)(p & 7)) << 4;
    const uint32_t* ei = sEt2 + i;
    const uint32_t* ej = sEt2 + j;
    #pragma unroll
    for (int c = 0; c < 8; c++) {
        uint32_t w[4];
        #pragma unroll
        for (int u = 0; u < 4; u++) {
            int s = c * 4 + u;                   // covers d = 2s, 2s+1
            w[u] = mulbf2(ei[s * 33], ej[s * 33]);
        }
        sts128(rowbase + (((uint32_t)(c * 16)) ^ xr), w[0], w[1], w[2], w[3]);
    }
}

__global__ __launch_bounds__(256, 2)
void afm_mma_kernel(const int*   __restrict__ x,
                    const float* __restrict__ emb,
                    const float* __restrict__ lin,
                    const float* __restrict__ lin_bias,
                    const float* __restrict__ W1,
                    const float* __restrict__ b1,
                    const float* __restrict__ w2,
                    const float* __restrict__ pw,
                    float*       __restrict__ out,
                    int BATCH)
{
    extern __shared__ char smem[];
    const uint32_t sb = s2u(smem);
    const int t    = threadIdx.x;
    const int wid  = t >> 5;
    const int lane = t & 31;

    float*    sS    = (float*)(smem + OFF_S);
    float*    sQ    = (float*)(smem + OFF_Q);
    float*    sRed  = (float*)(smem + OFF_RED);
    float*    sRedB = (float*)(smem + OFF_REDB);
    uint32_t* sEt2  = (uint32_t*)(smem + OFF_ET);
    float*    sFirst= (float*)(smem + OFF_FIRST);

    // ---- one-time init ----
    if (t >= 240) { sS[t + 256] = -1e30f; sQ[t + 256] = 0.f; }   // softmax pads (persist)
    for (int e = t; e < 512; e += 256)                            // zero P pad rows 496..511
        *(uint32_t*)(smem + OFF_P + 496 * 128 + e * 4) = 0u;

    // ---- W1 (+ proj_w as n-tile 4) as permanent B-fragments ----
    // m16n8k16 col-major B: lane -> n = nt*8 + lane/4, k = ks*16 + (lane%4)*2 (+8 for reg1)
    uint32_t bfrag[5][4][2];
    {
        int n  = (lane >> 2);
        int kk = (lane & 3) * 2;
        #pragma unroll
        for (int ks = 0; ks < 4; ks++) {
            #pragma unroll
            for (int nt = 0; nt < 4; nt++) {
                int k = ks * 16 + kk, col = nt * 8 + n;
                bfrag[nt][ks][0] = bfpair(W1[(k    ) * 32 + col], W1[(k + 1) * 32 + col]);
                bfrag[nt][ks][1] = bfpair(W1[(k + 8) * 32 + col], W1[(k + 9) * 32 + col]);
            }
            // n-tile 4: col 32 = proj_w, cols 33..39 = 0
            int k = ks * 16 + kk;
            bfrag[4][ks][0] = (n == 0) ? bfpair(pw[k],     pw[k + 1]) : 0u;
            bfrag[4][ks][1] = (n == 0) ? bfpair(pw[k + 8], pw[k + 9]) : 0u;
        }
    }
    float b1r[4][2], w2r[4][2];
    {
        int c0 = (lane & 3) * 2;
        #pragma unroll
        for (int nt = 0; nt < 4; nt++) {
            b1r[nt][0] = b1[nt * 8 + c0]; b1r[nt][1] = b1[nt * 8 + c0 + 1];
            w2r[nt][0] = w2[nt * 8 + c0]; w2r[nt][1] = w2[nt * 8 + c0 + 1];
        }
    }

    const float lbias = lin_bias[0];
    const uint32_t pbase = sb + OFF_P;

    // pair decode (triu order, i<j)
    int ia, ja, ib, jb;
    { int p = t, i = 0, c = 31; while (p >= c) { p -= c; c--; i++; } ia = i; ja = i + 1 + p; }
    const bool hasB = (t < NPAIRS - 256);
    { int p = t + 256, i = 0, c = 31; if (hasB) { while (p >= c) { p -= c; c--; i++; } ib = i; jb = i + 1 + p; } else { ib = 0; jb = 1; } }

    const int wbase = wid * 64;
    __syncthreads();

    for (int b = blockIdx.x; b < BATCH; b += gridDim.x) {
        // ---- gather embeddings -> bf16x2-packed transposed SMEM ----
        {
            int f = t >> 3, k = t & 7;
            int id = x[b * NUM_FIELDS + f] + f * FIELD_DIM;
            const float4* src = (const float4*)(emb + (size_t)id * EMB_DIM + k * 8);
            float4 v0 = src[0], v1 = src[1];
            int s0 = k * 4;
            sEt2[(s0+0)*33 + f] = bfpair(v0.x, v0.y);
            sEt2[(s0+1)*33 + f] = bfpair(v0.z, v0.w);
            sEt2[(s0+2)*33 + f] = bfpair(v1.x, v1.y);
            sEt2[(s0+3)*33 + f] = bfpair(v1.z, v1.w);
        }
        if (t < 32) {   // first-order linear term (fp32 exact)
            int id = x[b * NUM_FIELDS + t] + t * FIELD_DIM;
            float v = lin[id];
            #pragma unroll
            for (int off = 16; off; off >>= 1) v += __shfl_down_sync(0xffffffffu, v, off);
            if (t == 0) *sFirst = v + lbias;
        }
        __syncthreads();

        // ---- build bf16 P rows ----
        build_row(sEt2, pbase, ia, ja, t);
        if (hasB) build_row(sEt2, pbase, ib, jb, t + 256);
        __syncthreads();

        // ---- per-warp GEMM: 64 rows x 40 cols (32 att + q col), K=64 ----
        #pragma unroll
        for (int half = 0; half < 2; half++) {
            float acc[2][5][4];
            #pragma unroll
            for (int m = 0; m < 2; m++)
                #pragma unroll
                for (int nt = 0; nt < 5; nt++)
                    #pragma unroll
                    for (int v = 0; v < 4; v++) acc[m][nt][v] = 0.f;

            #pragma unroll
            for (int ks = 0; ks < 4; ks++) {
                #pragma unroll
                for (int mt = 0; mt < 2; mt++) {
                    int row  = wbase + half * 32 + mt * 16 + ((lane >> 3) & 1) * 8 + (lane & 7);
                    int ch   = ks * 2 + (lane >> 4);
                    uint32_t addr = pbase + (((uint32_t)(row * 128 + ch * 16)) ^ (((uint32_t)(row & 7)) << 4));
                    uint32_t a0, a1, a2, a3;
                    ldmatrix_x4(a0, a1, a2, a3, addr);
                    #pragma unroll
                    for (int nt = 0; nt < 5; nt++)
                        mma16816(acc[mt][nt], a0, a1, a2, a3, bfrag[nt][ks][0], bfrag[nt][ks][1]);
                }
            }

            // epilogue: relu + w2 dot + quad reduce -> scores; q from n-tile 4
            #pragma unroll
            for (int mt = 0; mt < 2; mt++) {
                #pragma unroll
                for (int rh = 0; rh < 2; rh++) {
                    float sp = 0.f;
                    #pragma unroll
                    for (int nt = 0; nt < 4; nt++) {
                        float v0 = acc[mt][nt][rh * 2 + 0];
                        float v1 = acc[mt][nt][rh * 2 + 1];
                        sp = fmaf(w2r[nt][0], fmaxf(v0 + b1r[nt][0], 0.f), sp);
                        sp = fmaf(w2r[nt][1], fmaxf(v1 + b1r[nt][1], 0.f), sp);
                    }
                    sp += __shfl_xor_sync(0xffffffffu, sp, 1);
                    sp += __shfl_xor_sync(0xffffffffu, sp, 2);
                    int pair = wbase + half * 32 + mt * 16 + rh * 8 + (lane >> 2);
                    if ((lane & 3) == 0 && pair < NPAIRS) {
                        sS[pair] = sp;
                        sQ[pair] = acc[mt][4][rh * 2];   // col 32 = q_p (lane%4==0 owns it)
                    }
                }
            }
        }
        __syncthreads();

        // ---- softmax over 496 + attn-weighted sum of q (shfl reductions) ----
        float s0 = sS[t], s1 = sS[t + 256];
        float m = fmaxf(s0, s1);
        #pragma unroll
        for (int off = 16; off; off >>= 1) m = fmaxf(m, __shfl_xor_sync(0xffffffffu, m, off));
        if (lane == 0) sRed[wid] = m;
        __syncthreads();

        float mx = sRed[0];
        #pragma unroll
        for (int w = 1; w < 8; w++) mx = fmaxf(mx, sRed[w]);

        float e0 = __expf(s0 - mx);
        float e1 = (t < 240) ? __expf(s1 - mx) : 0.f;
        float r  = e0 + e1;
        float rb = e0 * sQ[t] + e1 * sQ[t + 256];
        #pragma unroll
        for (int off = 16; off; off >>= 1) {
            r  += __shfl_xor_sync(0xffffffffu, r,  off);
            rb += __shfl_xor_sync(0xffffffffu, rb, off);
        }
        if (lane == 0) { sRed[8 + wid] = r; sRedB[wid] = rb; }
        __syncthreads();

        if (t == 0) {
            float R = 0.f, RB = 0.f;
            #pragma unroll
            for (int w = 0; w < 8; w++) { R += sRed[8 + w]; RB += sRedB[w]; }
            float y = *sFirst + RB / R;
            out[b] = 1.f / (1.f + __expf(-y));
        }
        __syncthreads();
    }
}

extern "C" void kernel_launch(void* const* d_in, const int* in_sizes, int n_in,
                              void* d_out, int out_size)
{
    const int*   x   = (const int*)  d_in[0];
    const float* emb = (const float*)d_in[1];
    const float* lin = (const float*)d_in[2];
    const float* lb  = (const float*)d_in[3];
    const float* W1  = (const float*)d_in[4];
    const float* b1  = (const float*)d_in[5];
    const float* w2  = (const float*)d_in[6];
    const float* pwv = (const float*)d_in[7];
    const int B = in_sizes[0] / NUM_FIELDS;

    cudaFuncSetAttribute(afm_mma_kernel, cudaFuncAttributeMaxDynamicSharedMemorySize, SMEM_TOTAL);
    int grid = GRID_CTAS < B ? GRID_CTAS : B;
    afm_mma_kernel<<<grid, 256, SMEM_TOTAL>>>(x, emb, lin, lb, W1, b1, w2, pwv, (float*)d_out, B);
}

// round 8
// speedup vs baseline: 3.1722x; 1.0352x over previous
#include <cuda_runtime.h>
#include <cuda_bf16.h>
#include <math.h>
#include <stdint.h>

#define NUM_FIELDS 32
#define FIELD_DIM  50000
#define EMB_DIM    64
#define ATT_DIM    32
#define NPAIRS     496
#define GRID_CTAS  296

// ---- dynamic smem layout (bytes) ----
#define OFF_FIRST  0
#define OFF_S      16      // 512 f32 (pads 496..511 = -1e30)
#define OFF_Q      2064    // 512 f32 (pads = 0)
#define OFF_RED    4112    // 24 f32: [0..7] max, [8..15] r, [16..23] rb
#define OFF_ET     4224    // 32*33 u32 bf16x2-packed Et
#define SMEM_TOTAL 8448

__device__ __forceinline__ uint32_t s2u(const void* p){
    uint32_t a; asm("{ .reg .u64 t; cvta.to.shared.u64 t, %1; cvt.u32.u64 %0, t; }":"=r"(a):"l"(p)); return a;
}
__device__ __forceinline__ uint32_t bfpair(float lo, float hi){
    uint32_t r; asm("cvt.rn.bf16x2.f32 %0, %1, %2;":"=r"(r):"f"(hi),"f"(lo)); return r;
}
__device__ __forceinline__ uint32_t mulbf2(uint32_t a, uint32_t b){
    uint32_t r; asm("mul.bf16x2 %0, %1, %2;":"=r"(r):"r"(a),"r"(b)); return r;
}
__device__ __forceinline__ uint32_t lds32(uint32_t a){
    uint32_t v; asm volatile("ld.shared.b32 %0, [%1];":"=r"(v):"r"(a)); return v;
}
__device__ __forceinline__ void mma16816(float* c, uint32_t a0, uint32_t a1, uint32_t a2, uint32_t a3,
                                         uint32_t b0, uint32_t b1){
    asm volatile("mma.sync.aligned.m16n8k16.row.col.f32.bf16.bf16.f32 "
                 "{%0,%1,%2,%3}, {%4,%5,%6,%7}, {%8,%9}, {%0,%1,%2,%3};"
                 : "+f"(c[0]),"+f"(c[1]),"+f"(c[2]),"+f"(c[3])
                 : "r"(a0),"r"(a1),"r"(a2),"r"(a3),"r"(b0),"r"(b1));
}

__device__ __forceinline__ void decode_pair(int p, int &i, int &j){
    int c = 31, ii = 0;
    while (p >= c) { p -= c; c--; ii++; }
    i = ii; j = ii + 1 + p;
}

__global__ __launch_bounds__(256, 2)
void afm_mma_kernel(const int*   __restrict__ x,
                    const float* __restrict__ emb,
                    const float* __restrict__ lin,
                    const float* __restrict__ lin_bias,
                    const float* __restrict__ W1,
                    const float* __restrict__ b1,
                    const float* __restrict__ w2,
                    const float* __restrict__ pw,
                    float*       __restrict__ out,
                    int BATCH)
{
    extern __shared__ char smem[];
    const uint32_t sb  = s2u(smem);
    const uint32_t etb = sb + OFF_ET;
    const int t    = threadIdx.x;
    const int wid  = t >> 5;
    const int lane = t & 31;

    float*    sS    = (float*)(smem + OFF_S);
    float*    sQ    = (float*)(smem + OFF_Q);
    float*    sRed  = (float*)(smem + OFF_RED);
    uint32_t* sEt2  = (uint32_t*)(smem + OFF_ET);
    float*    sFirst= (float*)(smem + OFF_FIRST);

    if (t >= 240) { sS[t + 256] = -1e30f; sQ[t + 256] = 0.f; }   // softmax pads (persist)

    // ---- W1 (+ proj_w as n-tile 4) as permanent B-fragments ----
    uint32_t bfrag[5][4][2];
    {
        int n  = (lane >> 2);
        int kk = (lane & 3) * 2;
        #pragma unroll
        for (int ks = 0; ks < 4; ks++) {
            #pragma unroll
            for (int nt = 0; nt < 4; nt++) {
                int k = ks * 16 + kk, col = nt * 8 + n;
                bfrag[nt][ks][0] = bfpair(W1[(k    ) * 32 + col], W1[(k + 1) * 32 + col]);
                bfrag[nt][ks][1] = bfpair(W1[(k + 8) * 32 + col], W1[(k + 9) * 32 + col]);
            }
            int k = ks * 16 + kk;
            bfrag[4][ks][0] = (n == 0) ? bfpair(pw[k],     pw[k + 1]) : 0u;
            bfrag[4][ks][1] = (n == 0) ? bfpair(pw[k + 8], pw[k + 9]) : 0u;
        }
    }
    float b1r[4][2], w2r[4][2];
    {
        int c0 = (lane & 3) * 2;
        #pragma unroll
        for (int nt = 0; nt < 4; nt++) {
            b1r[nt][0] = b1[nt * 8 + c0]; b1r[nt][1] = b1[nt * 8 + c0 + 1];
            w2r[nt][0] = w2[nt * 8 + c0]; w2r[nt][1] = w2[nt * 8 + c0 + 1];
        }
    }

    // ---- per-thread pair rows for the 4 M-tiles (decode once) ----
    // tile tl: rows base_t + lane/4 and +8, base_t = wid*64 + (tl>>1)*32 + (tl&1)*16
    uint32_t oi1[4], oj1[4], oi2[4], oj2[4];
    #pragma unroll
    for (int tl = 0; tl < 4; tl++) {
        int base_t = wid * 64 + (tl >> 1) * 32 + (tl & 1) * 16;
        int r1 = base_t + (lane >> 2), r2 = r1 + 8;
        int i1 = 0, j1 = 1, i2 = 0, j2 = 1;
        if (r1 < NPAIRS) decode_pair(r1, i1, j1);
        if (r2 < NPAIRS) decode_pair(r2, i2, j2);
        oi1[tl] = (uint32_t)i1 * 4; oj1[tl] = (uint32_t)j1 * 4;
        oi2[tl] = (uint32_t)i2 * 4; oj2[tl] = (uint32_t)j2 * 4;
    }

    const float lbias = lin_bias[0];
    const int f = t >> 3, k8 = t & 7;

    // ---- prefetch first sample ----
    float4 pf0, pf1; float pfl = 0.f;
    {
        int id = x[blockIdx.x * NUM_FIELDS + f] + f * FIELD_DIM;
        const float4* src = (const float4*)(emb + (size_t)id * EMB_DIM + k8 * 8);
        pf0 = src[0]; pf1 = src[1];
        if (t < 32) pfl = lin[x[blockIdx.x * NUM_FIELDS + t] + t * FIELD_DIM];
    }
    __syncthreads();

    for (int b = blockIdx.x; b < BATCH; b += gridDim.x) {
        // ---- store prefetched embeddings -> bf16x2 transposed SMEM ----
        {
            int s0 = k8 * 4;
            sEt2[(s0+0)*33 + f] = bfpair(pf0.x, pf0.y);
            sEt2[(s0+1)*33 + f] = bfpair(pf0.z, pf0.w);
            sEt2[(s0+2)*33 + f] = bfpair(pf1.x, pf1.y);
            sEt2[(s0+3)*33 + f] = bfpair(pf1.z, pf1.w);
        }
        if (t < 32) {   // first-order linear term (fp32 exact)
            float v = pfl;
            #pragma unroll
            for (int off = 16; off; off >>= 1) v += __shfl_down_sync(0xffffffffu, v, off);
            if (t == 0) *sFirst = v + lbias;
        }
        __syncthreads();

        // ---- prefetch next sample (latency hidden behind compute) ----
        {
            int nb = b + gridDim.x;
            if (nb < BATCH) {
                int id = x[nb * NUM_FIELDS + f] + f * FIELD_DIM;
                const float4* src = (const float4*)(emb + (size_t)id * EMB_DIM + k8 * 8);
                pf0 = src[0]; pf1 = src[1];
                if (t < 32) pfl = lin[x[nb * NUM_FIELDS + t] + t * FIELD_DIM];
            }
        }

        // ---- 4 M-tiles: A-fragments straight from registers, 5 N-tiles ----
        #pragma unroll
        for (int tl = 0; tl < 4; tl++) {
            float acc[5][4];
            #pragma unroll
            for (int nt = 0; nt < 5; nt++)
                #pragma unroll
                for (int v = 0; v < 4; v++) acc[nt][v] = 0.f;

            #pragma unroll
            for (int ks = 0; ks < 4; ks++) {
                uint32_t so = etb + (uint32_t)(ks * 8 + (lane & 3)) * 132;
                uint32_t a0 = mulbf2(lds32(so + oi1[tl]),       lds32(so + oj1[tl]));
                uint32_t a1 = mulbf2(lds32(so + oi2[tl]),       lds32(so + oj2[tl]));
                uint32_t a2 = mulbf2(lds32(so + 528 + oi1[tl]), lds32(so + 528 + oj1[tl]));
                uint32_t a3 = mulbf2(lds32(so + 528 + oi2[tl]), lds32(so + 528 + oj2[tl]));
                #pragma unroll
                for (int nt = 0; nt < 5; nt++)
                    mma16816(acc[nt], a0, a1, a2, a3, bfrag[nt][ks][0], bfrag[nt][ks][1]);
            }

            // epilogue: relu + w2 dot + quad reduce -> scores; q from n-tile 4
            int base_t = wid * 64 + (tl >> 1) * 32 + (tl & 1) * 16;
            #pragma unroll
            for (int rh = 0; rh < 2; rh++) {
                float sp = 0.f;
                #pragma unroll
                for (int nt = 0; nt < 4; nt++) {
                    float v0 = acc[nt][rh * 2 + 0];
                    float v1 = acc[nt][rh * 2 + 1];
                    sp = fmaf(w2r[nt][0], fmaxf(v0 + b1r[nt][0], 0.f), sp);
                    sp = fmaf(w2r[nt][1], fmaxf(v1 + b1r[nt][1], 0.f), sp);
                }
                sp += __shfl_xor_sync(0xffffffffu, sp, 1);
                sp += __shfl_xor_sync(0xffffffffu, sp, 2);
                int pair = base_t + rh * 8 + (lane >> 2);
                if ((lane & 3) == 0 && pair < NPAIRS) {
                    sS[pair] = sp;
                    sQ[pair] = acc[4][rh * 2];
                }
            }
        }
        __syncthreads();

        // ---- softmax over 496 + attn-weighted sum of q (shfl reductions) ----
        float s0 = sS[t], s1 = sS[t + 256];
        float m = fmaxf(s0, s1);
        #pragma unroll
        for (int off = 16; off; off >>= 1) m = fmaxf(m, __shfl_xor_sync(0xffffffffu, m, off));
        if (lane == 0) sRed[wid] = m;
        __syncthreads();

        float mx = sRed[0];
        #pragma unroll
        for (int w = 1; w < 8; w++) mx = fmaxf(mx, sRed[w]);

        float e0 = __expf(s0 - mx);
        float e1 = (t < 240) ? __expf(s1 - mx) : 0.f;
        float r  = e0 + e1;
        float rb = e0 * sQ[t] + e1 * sQ[t + 256];
        #pragma unroll
        for (int off = 16; off; off >>= 1) {
            r  += __shfl_xor_sync(0xffffffffu, r,  off);
            rb += __shfl_xor_sync(0xffffffffu, rb, off);
        }
        if (lane == 0) { sRed[8 + wid] = r; sRed[16 + wid] = rb; }
        __syncthreads();

        if (t == 0) {
            float R = 0.f, RB = 0.f;
            #pragma unroll
            for (int w = 0; w < 8; w++) { R += sRed[8 + w]; RB += sRed[16 + w]; }
            float y = *sFirst + RB / R;
            out[b] = 1.f / (1.f + __expf(-y));
        }
        __syncthreads();
    }
}

extern "C" void kernel_launch(void* const* d_in, const int* in_sizes, int n_in,
                              void* d_out, int out_size)
{
    const int*   x   = (const int*)  d_in[0];
    const float* emb = (const float*)d_in[1];
    const float* lin = (const float*)d_in[2];
    const float* lb  = (const float*)d_in[3];
    const float* W1  = (const float*)d_in[4];
    const float* b1  = (const float*)d_in[5];
    const float* w2  = (const float*)d_in[6];
    const float* pwv = (const float*)d_in[7];
    const int B = in_sizes[0] / NUM_FIELDS;

    cudaFuncSetAttribute(afm_mma_kernel, cudaFuncAttributeMaxDynamicSharedMemorySize, SMEM_TOTAL);
    int grid = GRID_CTAS < B ? GRID_CTAS : B;
    afm_mma_kernel<<<grid, 256, SMEM_TOTAL>>>(x, emb, lin, lb, W1, b1, w2, pwv, (float*)d_out, B);
}

// round 9
// speedup vs baseline: 4.1316x; 1.3024x over previous
#include <cuda_runtime.h>
#include <cuda_bf16.h>
#include <math.h>
#include <stdint.h>

#define NUM_FIELDS 32
#define FIELD_DIM  50000
#define EMB_DIM    64
#define ATT_DIM    32
#define NPAIRS     496
#define GRID_CTAS  296

// ---- dynamic smem layout (bytes) ----
#define OFF_FIRST  0
#define OFF_S      16      // 512 f32 (pads 496..511 = -1e30)
#define OFF_Q      2064    // 512 f32 (pads = 0)
#define OFF_RED    4112    // 24 f32
#define OFF_ET     4224    // Et[f][w]: 32 fields x 36 u32 (K-permuted bf16x2) = 4608 B
#define SMEM_TOTAL 8832
#define ET_FSTRIDE 144     // 36 words * 4B; 4f mod 32 bank coefficient

__device__ __forceinline__ uint32_t s2u(const void* p){
    uint32_t a; asm("{ .reg .u64 t; cvta.to.shared.u64 t, %1; cvt.u32.u64 %0, t; }":"=r"(a):"l"(p)); return a;
}
__device__ __forceinline__ uint32_t bfpair(float lo, float hi){
    uint32_t r; asm("cvt.rn.bf16x2.f32 %0, %1, %2;":"=r"(r):"f"(hi),"f"(lo)); return r;
}
__device__ __forceinline__ uint32_t mulbf2(uint32_t a, uint32_t b){
    uint32_t r; asm("mul.bf16x2 %0, %1, %2;":"=r"(r):"r"(a),"r"(b)); return r;
}
__device__ __forceinline__ void lds128(uint32_t a, uint32_t* v){
    asm volatile("ld.shared.v4.b32 {%0,%1,%2,%3}, [%4];"
                 :"=r"(v[0]),"=r"(v[1]),"=r"(v[2]),"=r"(v[3]):"r"(a));
}
__device__ __forceinline__ void mma16816(float* c, uint32_t a0, uint32_t a1, uint32_t a2, uint32_t a3,
                                         uint32_t b0, uint32_t b1){
    asm volatile("mma.sync.aligned.m16n8k16.row.col.f32.bf16.bf16.f32 "
                 "{%0,%1,%2,%3}, {%4,%5,%6,%7}, {%8,%9}, {%0,%1,%2,%3};"
                 : "+f"(c[0]),"+f"(c[1]),"+f"(c[2]),"+f"(c[3])
                 : "r"(a0),"r"(a1),"r"(a2),"r"(a3),"r"(b0),"r"(b1));
}

__device__ __forceinline__ void decode_pair(int p, int &i, int &j){
    int c = 31, ii = 0;
    while (p >= c) { p -= c; c--; ii++; }
    i = ii; j = ii + 1 + p;
}

__global__ __launch_bounds__(256, 2)
void afm_mma_kernel(const int*   __restrict__ x,
                    const float* __restrict__ emb,
                    const float* __restrict__ lin,
                    const float* __restrict__ lin_bias,
                    const float* __restrict__ W1,
                    const float* __restrict__ b1,
                    const float* __restrict__ w2,
                    const float* __restrict__ pw,
                    float*       __restrict__ out,
                    int BATCH)
{
    extern __shared__ char smem[];
    const uint32_t sb  = s2u(smem);
    const uint32_t etb = sb + OFF_ET;
    const int t    = threadIdx.x;
    const int wid  = t >> 5;
    const int lane = t & 31;

    float*    sS    = (float*)(smem + OFF_S);
    float*    sQ    = (float*)(smem + OFF_Q);
    float*    sRed  = (float*)(smem + OFF_RED);
    uint32_t* sEt   = (uint32_t*)(smem + OFF_ET);
    float*    sFirst= (float*)(smem + OFF_FIRST);

    if (t >= 240) { sS[t + 256] = -1e30f; sQ[t + 256] = 0.f; }   // softmax pads (persist)

    // ---- W1 (+ proj_w as n-tile 4) as permanent B-fragments (logical k indexing) ----
    uint32_t bfrag[5][4][2];
    {
        int n  = (lane >> 2);
        int kk = (lane & 3) * 2;
        #pragma unroll
        for (int ks = 0; ks < 4; ks++) {
            #pragma unroll
            for (int nt = 0; nt < 4; nt++) {
                int k = ks * 16 + kk, col = nt * 8 + n;
                bfrag[nt][ks][0] = bfpair(W1[(k    ) * 32 + col], W1[(k + 1) * 32 + col]);
                bfrag[nt][ks][1] = bfpair(W1[(k + 8) * 32 + col], W1[(k + 9) * 32 + col]);
            }
            int k = ks * 16 + kk;
            bfrag[4][ks][0] = (n == 0) ? bfpair(pw[k],     pw[k + 1]) : 0u;
            bfrag[4][ks][1] = (n == 0) ? bfpair(pw[k + 8], pw[k + 9]) : 0u;
        }
    }
    float b1r[4][2], w2r[4][2];
    {
        int c0 = (lane & 3) * 2;
        #pragma unroll
        for (int nt = 0; nt < 4; nt++) {
            b1r[nt][0] = b1[nt * 8 + c0]; b1r[nt][1] = b1[nt * 8 + c0 + 1];
            w2r[nt][0] = w2[nt * 8 + c0]; w2r[nt][1] = w2[nt * 8 + c0 + 1];
        }
    }

    // ---- per-thread pair rows for the 4 M-tiles; byte offsets packed u16 ----
    uint32_t po1[4], po2[4];   // lo16 = i*144, hi16 = j*144
    #pragma unroll
    for (int tl = 0; tl < 4; tl++) {
        int base_t = wid * 64 + (tl >> 1) * 32 + (tl & 1) * 16;
        int r1 = base_t + (lane >> 2), r2 = r1 + 8;
        int i1 = 0, j1 = 1, i2 = 0, j2 = 1;
        if (r1 < NPAIRS) decode_pair(r1, i1, j1);
        if (r2 < NPAIRS) decode_pair(r2, i2, j2);
        po1[tl] = (uint32_t)(i1 * ET_FSTRIDE) | ((uint32_t)(j1 * ET_FSTRIDE) << 16);
        po2[tl] = (uint32_t)(i2 * ET_FSTRIDE) | ((uint32_t)(j2 * ET_FSTRIDE) << 16);
    }

    const float lbias = lin_bias[0];
    const int f = t >> 3, k8 = t & 7;
    const uint32_t ebase = etb + (uint32_t)(lane & 3) * 32;  // + 8*kk words

    // ---- prefetch first sample ----
    float4 pf0, pf1; float pfl = 0.f;
    {
        int id = x[blockIdx.x * NUM_FIELDS + f] + f * FIELD_DIM;
        const float4* src = (const float4*)(emb + (size_t)id * EMB_DIM + k8 * 8);
        pf0 = src[0]; pf1 = src[1];
        if (t < 32) pfl = lin[x[blockIdx.x * NUM_FIELDS + t] + t * FIELD_DIM];
    }
    __syncthreads();

    for (int b = blockIdx.x; b < BATCH; b += gridDim.x) {
        // ---- store prefetched embeddings, K-permuted: logical word l=4*k8+u -> phys 8u+k8 ----
        {
            uint32_t base = (uint32_t)f * 36 + (uint32_t)k8;
            sEt[base     ] = bfpair(pf0.x, pf0.y);
            sEt[base +  8] = bfpair(pf0.z, pf0.w);
            sEt[base + 16] = bfpair(pf1.x, pf1.y);
            sEt[base + 24] = bfpair(pf1.z, pf1.w);
        }
        if (t < 32) {   // first-order linear term (fp32 exact)
            float v = pfl;
            #pragma unroll
            for (int off = 16; off; off >>= 1) v += __shfl_down_sync(0xffffffffu, v, off);
            if (t == 0) *sFirst = v + lbias;
        }
        __syncthreads();

        // ---- prefetch next sample (hidden behind compute) ----
        {
            int nb = b + gridDim.x;
            if (nb < BATCH) {
                int id = x[nb * NUM_FIELDS + f] + f * FIELD_DIM;
                const float4* src = (const float4*)(emb + (size_t)id * EMB_DIM + k8 * 8);
                pf0 = src[0]; pf1 = src[1];
                if (t < 32) pfl = lin[x[nb * NUM_FIELDS + t] + t * FIELD_DIM];
            }
        }

        // ---- 4 M-tiles: vectorized conflict-free fragment build, 5 N-tiles ----
        #pragma unroll
        for (int tl = 0; tl < 4; tl++) {
            uint32_t Ei1[8], Ej1[8], Ei2[8], Ej2[8];
            {
                uint32_t o1 = po1[tl], o2 = po2[tl];
                uint32_t ai = ebase + (o1 & 0xffffu), aj = ebase + (o1 >> 16);
                lds128(ai, Ei1); lds128(ai + 16, Ei1 + 4);
                lds128(aj, Ej1); lds128(aj + 16, Ej1 + 4);
                ai = ebase + (o2 & 0xffffu); aj = ebase + (o2 >> 16);
                lds128(ai, Ei2); lds128(ai + 16, Ei2 + 4);
                lds128(aj, Ej2); lds128(aj + 16, Ej2 + 4);
            }

            float acc[5][4];
            #pragma unroll
            for (int nt = 0; nt < 5; nt++)
                #pragma unroll
                for (int v = 0; v < 4; v++) acc[nt][v] = 0.f;

            #pragma unroll
            for (int ks = 0; ks < 4; ks++) {
                uint32_t a0 = mulbf2(Ei1[2*ks    ], Ej1[2*ks    ]);
                uint32_t a1 = mulbf2(Ei2[2*ks    ], Ej2[2*ks    ]);
                uint32_t a2 = mulbf2(Ei1[2*ks + 1], Ej1[2*ks + 1]);
                uint32_t a3 = mulbf2(Ei2[2*ks + 1], Ej2[2*ks + 1]);
                #pragma unroll
                for (int nt = 0; nt < 5; nt++)
                    mma16816(acc[nt], a0, a1, a2, a3, bfrag[nt][ks][0], bfrag[nt][ks][1]);
            }

            // epilogue: relu + w2 dot + quad reduce -> scores; q from n-tile 4
            int base_t = wid * 64 + (tl >> 1) * 32 + (tl & 1) * 16;
            #pragma unroll
            for (int rh = 0; rh < 2; rh++) {
                float sp = 0.f;
                #pragma unroll
                for (int nt = 0; nt < 4; nt++) {
                    float v0 = acc[nt][rh * 2 + 0];
                    float v1 = acc[nt][rh * 2 + 1];
                    sp = fmaf(w2r[nt][0], fmaxf(v0 + b1r[nt][0], 0.f), sp);
                    sp = fmaf(w2r[nt][1], fmaxf(v1 + b1r[nt][1], 0.f), sp);
                }
                sp += __shfl_xor_sync(0xffffffffu, sp, 1);
                sp += __shfl_xor_sync(0xffffffffu, sp, 2);
                int pair = base_t + rh * 8 + (lane >> 2);
                if ((lane & 3) == 0 && pair < NPAIRS) {
                    sS[pair] = sp;
                    sQ[pair] = acc[4][rh * 2];
                }
            }
        }
        __syncthreads();

        // ---- softmax over 496 + attn-weighted sum of q (shfl reductions) ----
        float s0 = sS[t], s1 = sS[t + 256];
        float m = fmaxf(s0, s1);
        #pragma unroll
        for (int off = 16; off; off >>= 1) m = fmaxf(m, __shfl_xor_sync(0xffffffffu, m, off));
        if (lane == 0) sRed[wid] = m;
        __syncthreads();

        float mx = sRed[0];
        #pragma unroll
        for (int w = 1; w < 8; w++) mx = fmaxf(mx, sRed[w]);

        float e0 = __expf(s0 - mx);
        float e1 = (t < 240) ? __expf(s1 - mx) : 0.f;
        float r  = e0 + e1;
        float rb = e0 * sQ[t] + e1 * sQ[t + 256];
        #pragma unroll
        for (int off = 16; off; off >>= 1) {
            r  += __shfl_xor_sync(0xffffffffu, r,  off);
            rb += __shfl_xor_sync(0xffffffffu, rb, off);
        }
        if (lane == 0) { sRed[8 + wid] = r; sRed[16 + wid] = rb; }
        __syncthreads();

        if (t == 0) {
            float R = 0.f, RB = 0.f;
            #pragma unroll
            for (int w = 0; w < 8; w++) { R += sRed[8 + w]; RB += sRed[16 + w]; }
            float y = *sFirst + RB / R;
            out[b] = 1.f / (1.f + __expf(-y));
        }
        __syncthreads();
    }
}

extern "C" void kernel_launch(void* const* d_in, const int* in_sizes, int n_in,
                              void* d_out, int out_size)
{
    const int*   x   = (const int*)  d_in[0];
    const float* emb = (const float*)d_in[1];
    const float* lin = (const float*)d_in[2];
    const float* lb  = (const float*)d_in[3];
    const float* W1  = (const float*)d_in[4];
    const float* b1  = (const float*)d_in[5];
    const float* w2  = (const float*)d_in[6];
    const float* pwv = (const float*)d_in[7];
    const int B = in_sizes[0] / NUM_FIELDS;

    cudaFuncSetAttribute(afm_mma_kernel, cudaFuncAttributeMaxDynamicSharedMemorySize, SMEM_TOTAL);
    int grid = GRID_CTAS < B ? GRID_CTAS : B;
    afm_mma_kernel<<<grid, 256, SMEM_TOTAL>>>(x, emb, lin, lb, W1, b1, w2, pwv, (float*)d_out, B);
}

// round 10
// speedup vs baseline: 4.8563x; 1.1754x over previous
#include <cuda_runtime.h>
#include <cuda_bf16.h>
#include <math.h>
#include <stdint.h>

#define NUM_FIELDS 32
#define FIELD_DIM  50000
#define EMB_DIM    64
#define ATT_DIM    32
#define NPAIRS     496
#define NTH        128
#define GRID_CTAS  592

// ---- dynamic smem layout (bytes) ----
#define OFF_S      0       // 512 f32 (pads 496..511 = -1e30)
#define OFF_Q      2048    // 512 f32 (pads = 0)
#define OFF_RED    4096    // 12 f32: per-warp (mx, r, rb)
#define OFF_LUT    4160    // 512 u32 packed pair offsets
#define OFF_ET     6208    // Et[f][w]: 32 fields x 36 u32 (K-permuted bf16x2)
#define SMEM_TOTAL 10816
#define ET_FSTRIDE 144     // 36 words * 4B

__device__ __forceinline__ uint32_t s2u(const void* p){
    uint32_t a; asm("{ .reg .u64 t; cvta.to.shared.u64 t, %1; cvt.u32.u64 %0, t; }":"=r"(a):"l"(p)); return a;
}
__device__ __forceinline__ uint32_t bfpair(float lo, float hi){
    uint32_t r; asm("cvt.rn.bf16x2.f32 %0, %1, %2;":"=r"(r):"f"(hi),"f"(lo)); return r;
}
__device__ __forceinline__ uint32_t mulbf2(uint32_t a, uint32_t b){
    uint32_t r; asm("mul.bf16x2 %0, %1, %2;":"=r"(r):"r"(a),"r"(b)); return r;
}
__device__ __forceinline__ uint32_t lds32(uint32_t a){
    uint32_t v; asm volatile("ld.shared.b32 %0, [%1];":"=r"(v):"r"(a)); return v;
}
__device__ __forceinline__ void lds128(uint32_t a, uint32_t* v){
    asm volatile("ld.shared.v4.b32 {%0,%1,%2,%3}, [%4];"
                 :"=r"(v[0]),"=r"(v[1]),"=r"(v[2]),"=r"(v[3]):"r"(a));
}
__device__ __forceinline__ void sts64(uint32_t a, uint32_t v0, uint32_t v1){
    asm volatile("st.shared.v2.b32 [%0], {%1,%2};"::"r"(a),"r"(v0),"r"(v1):"memory");
}
__device__ __forceinline__ void sts32(uint32_t a, uint32_t v){
    asm volatile("st.shared.b32 [%0], %1;"::"r"(a),"r"(v):"memory");
}
__device__ __forceinline__ void mma16816(float* c, uint32_t a0, uint32_t a1, uint32_t a2, uint32_t a3,
                                         uint32_t b0, uint32_t b1){
    asm volatile("mma.sync.aligned.m16n8k16.row.col.f32.bf16.bf16.f32 "
                 "{%0,%1,%2,%3}, {%4,%5,%6,%7}, {%8,%9}, {%0,%1,%2,%3};"
                 : "+f"(c[0]),"+f"(c[1]),"+f"(c[2]),"+f"(c[3])
                 : "r"(a0),"r"(a1),"r"(a2),"r"(a3),"r"(b0),"r"(b1));
}
__device__ __forceinline__ void decode_pair(int p, int &i, int &j){
    int c = 31, ii = 0;
    while (p >= c) { p -= c; c--; ii++; }
    i = ii; j = ii + 1 + p;
}

__global__ __launch_bounds__(NTH, 4)
void afm_mma_kernel(const int*   __restrict__ x,
                    const float* __restrict__ emb,
                    const float* __restrict__ lin,
                    const float* __restrict__ lin_bias,
                    const float* __restrict__ W1,
                    const float* __restrict__ b1,
                    const float* __restrict__ w2,
                    const float* __restrict__ pw,
                    float*       __restrict__ out,
                    int BATCH)
{
    extern __shared__ char smem[];
    const uint32_t sb  = s2u(smem);
    const uint32_t etb = sb + OFF_ET;
    const int t    = threadIdx.x;
    const int wid  = t >> 5;
    const int lane = t & 31;

    float*    sS   = (float*)(smem + OFF_S);
    float*    sQ   = (float*)(smem + OFF_Q);
    float*    sRed = (float*)(smem + OFF_RED);
    uint32_t* sLUT = (uint32_t*)(smem + OFF_LUT);
    uint32_t* sEt  = (uint32_t*)(smem + OFF_ET);

    // ---- one-time init ----
    if (t < 16) { sS[496 + t] = -1e30f; sQ[496 + t] = 0.f; }
    for (int p = t; p < 512; p += NTH) {
        int pp = (p < NPAIRS) ? p : 0;
        int i, j; decode_pair(pp, i, j);
        sLUT[p] = (uint32_t)(i * ET_FSTRIDE) | ((uint32_t)(j * ET_FSTRIDE) << 16);
    }

    // ---- W1 (+ proj_w as n-tile 4) as permanent B-fragments (logical k indexing) ----
    uint32_t bfrag[5][4][2];
    {
        int n  = (lane >> 2);
        int kk = (lane & 3) * 2;
        #pragma unroll
        for (int ks = 0; ks < 4; ks++) {
            #pragma unroll
            for (int nt = 0; nt < 4; nt++) {
                int k = ks * 16 + kk, col = nt * 8 + n;
                bfrag[nt][ks][0] = bfpair(W1[(k    ) * 32 + col], W1[(k + 1) * 32 + col]);
                bfrag[nt][ks][1] = bfpair(W1[(k + 8) * 32 + col], W1[(k + 9) * 32 + col]);
            }
            int k = ks * 16 + kk;
            bfrag[4][ks][0] = (n == 0) ? bfpair(pw[k],     pw[k + 1]) : 0u;
            bfrag[4][ks][1] = (n == 0) ? bfpair(pw[k + 8], pw[k + 9]) : 0u;
        }
    }
    float b1r[4][2], w2r[4][2];
    {
        int c0 = (lane & 3) * 2;
        #pragma unroll
        for (int nt = 0; nt < 4; nt++) {
            b1r[nt][0] = b1[nt * 8 + c0]; b1r[nt][1] = b1[nt * 8 + c0 + 1];
            w2r[nt][0] = w2[nt * 8 + c0]; w2r[nt][1] = w2[nt * 8 + c0 + 1];
        }
    }

    const float lbias = lin_bias[0];
    const int f = t >> 2, q4 = t & 3;
    const uint32_t ebase = etb + (uint32_t)(lane & 3) * 32;   // + 8*kk words
    const uint32_t lutb  = sb + OFF_LUT + ((uint32_t)(lane >> 2)) * 4;

    // ---- prefetch first sample: 16 floats per thread (4 threads/field) ----
    float4 pf0, pf1, pf2, pf3; float pfl = 0.f;
    {
        int id = x[blockIdx.x * NUM_FIELDS + f] + f * FIELD_DIM;
        const float4* src = (const float4*)(emb + (size_t)id * EMB_DIM + q4 * 16);
        pf0 = src[0]; pf1 = src[1]; pf2 = src[2]; pf3 = src[3];
        if (t < 32) pfl = lin[x[blockIdx.x * NUM_FIELDS + t] + t * FIELD_DIM];
    }
    float firstv = 0.f;
    __syncthreads();

    for (int b = blockIdx.x; b < BATCH; b += gridDim.x) {
        // ---- store prefetched embeddings, K-permuted (phys word = 8*(l&3) + l/4) ----
        {
            uint32_t wb = etb + ((uint32_t)f * 36 + 2u * q4) * 4;
            sts64(wb,       bfpair(pf0.x, pf0.y), bfpair(pf2.x, pf2.y));
            sts64(wb + 32,  bfpair(pf0.z, pf0.w), bfpair(pf2.z, pf2.w));
            sts64(wb + 64,  bfpair(pf1.x, pf1.y), bfpair(pf3.x, pf3.y));
            sts64(wb + 96,  bfpair(pf1.z, pf1.w), bfpair(pf3.z, pf3.w));
        }
        if (t < 32) {   // first-order linear term (fp32 exact)
            float v = pfl;
            #pragma unroll
            for (int off = 16; off; off >>= 1) v += __shfl_down_sync(0xffffffffu, v, off);
            if (t == 0) firstv = v + lbias;
        }
        __syncthreads();                                   // S1

        // ---- prefetch next sample (hidden behind compute) ----
        {
            int nb = b + gridDim.x;
            if (nb < BATCH) {
                int id = x[nb * NUM_FIELDS + f] + f * FIELD_DIM;
                const float4* src = (const float4*)(emb + (size_t)id * EMB_DIM + q4 * 16);
                pf0 = src[0]; pf1 = src[1]; pf2 = src[2]; pf3 = src[3];
                if (t < 32) pfl = lin[x[nb * NUM_FIELDS + t] + t * FIELD_DIM];
            }
        }

        // ---- 8 M-tiles per warp (interleaved across warps), 5 N-tiles ----
        #pragma unroll
        for (int tl = 0; tl < 8; tl++) {
            const int base_t = (tl * 4 + wid) * 16;
            uint32_t lo = lutb + (uint32_t)base_t * 4;
            uint32_t po1 = lds32(lo), po2 = lds32(lo + 32);

            uint32_t P1[8], P2[8];
            {
                uint32_t E[16];
                uint32_t ai = ebase + (po1 & 0xffffu), aj = ebase + (po1 >> 16);
                lds128(ai, E); lds128(ai + 16, E + 4);
                lds128(aj, E + 8); lds128(aj + 16, E + 12);
                #pragma unroll
                for (int c = 0; c < 8; c++) P1[c] = mulbf2(E[c], E[8 + c]);
                ai = ebase + (po2 & 0xffffu); aj = ebase + (po2 >> 16);
                lds128(ai, E); lds128(ai + 16, E + 4);
                lds128(aj, E + 8); lds128(aj + 16, E + 12);
                #pragma unroll
                for (int c = 0; c < 8; c++) P2[c] = mulbf2(E[c], E[8 + c]);
            }

            float acc[5][4];
            #pragma unroll
            for (int nt = 0; nt < 5; nt++)
                #pragma unroll
                for (int v = 0; v < 4; v++) acc[nt][v] = 0.f;

            #pragma unroll
            for (int ks = 0; ks < 4; ks++) {
                #pragma unroll
                for (int nt = 0; nt < 5; nt++)
                    mma16816(acc[nt], P1[2*ks], P2[2*ks], P1[2*ks+1], P2[2*ks+1],
                             bfrag[nt][ks][0], bfrag[nt][ks][1]);
            }

            // epilogue: relu + w2 dot + quad reduce -> scores; q from n-tile 4
            #pragma unroll
            for (int rh = 0; rh < 2; rh++) {
                float sp = 0.f;
                #pragma unroll
                for (int nt = 0; nt < 4; nt++) {
                    float v0 = acc[nt][rh * 2 + 0];
                    float v1 = acc[nt][rh * 2 + 1];
                    sp = fmaf(w2r[nt][0], fmaxf(v0 + b1r[nt][0], 0.f), sp);
                    sp = fmaf(w2r[nt][1], fmaxf(v1 + b1r[nt][1], 0.f), sp);
                }
                sp += __shfl_xor_sync(0xffffffffu, sp, 1);
                sp += __shfl_xor_sync(0xffffffffu, sp, 2);
                int pair = base_t + rh * 8 + (lane >> 2);
                if ((lane & 3) == 0 && pair < NPAIRS) {
                    sS[pair] = sp;
                    sQ[pair] = acc[4][rh * 2];
                }
            }
        }
        __syncthreads();                                   // S2

        // ---- per-warp softmax partials (own-max shift) ----
        {
            float s0 = sS[t], s1 = sS[t + 128], s2 = sS[t + 256], s3 = sS[t + 384];
            float q0 = sQ[t], q1 = sQ[t + 128], q2 = sQ[t + 256], q3 = sQ[t + 384];
            float m = fmaxf(fmaxf(s0, s1), fmaxf(s2, s3));
            #pragma unroll
            for (int off = 16; off; off >>= 1) m = fmaxf(m, __shfl_xor_sync(0xffffffffu, m, off));
            float e0 = __expf(s0 - m), e1 = __expf(s1 - m);
            float e2 = __expf(s2 - m), e3 = __expf(s3 - m);
            float r  = (e0 + e1) + (e2 + e3);
            float rb = fmaf(e0, q0, fmaf(e1, q1, fmaf(e2, q2, e3 * q3)));
            #pragma unroll
            for (int off = 16; off; off >>= 1) {
                r  += __shfl_xor_sync(0xffffffffu, r,  off);
                rb += __shfl_xor_sync(0xffffffffu, rb, off);
            }
            if (lane == 0) { sRed[wid * 3] = m; sRed[wid * 3 + 1] = r; sRed[wid * 3 + 2] = rb; }
        }
        __syncthreads();                                   // S3

        if (t == 0) {
            float MX = fmaxf(fmaxf(sRed[0], sRed[3]), fmaxf(sRed[6], sRed[9]));
            float R = 0.f, RB = 0.f;
            #pragma unroll
            for (int w = 0; w < 4; w++) {
                float sc = __expf(sRed[w * 3] - MX);
                R  = fmaf(sRed[w * 3 + 1], sc, R);
                RB = fmaf(sRed[w * 3 + 2], sc, RB);
            }
            float y = firstv + RB / R;
            out[b] = 1.f / (1.f + __expf(-y));
        }
    }
}

extern "C" void kernel_launch(void* const* d_in, const int* in_sizes, int n_in,
                              void* d_out, int out_size)
{
    const int*   x   = (const int*)  d_in[0];
    const float* emb = (const float*)d_in[1];
    const float* lin = (const float*)d_in[2];
    const float* lb  = (const float*)d_in[3];
    const float* W1  = (const float*)d_in[4];
    const float* b1  = (const float*)d_in[5];
    const float* w2  = (const float*)d_in[6];
    const float* pwv = (const float*)d_in[7];
    const int B = in_sizes[0] / NUM_FIELDS;

    cudaFuncSetAttribute(afm_mma_kernel, cudaFuncAttributeMaxDynamicSharedMemorySize, SMEM_TOTAL);
    int grid = GRID_CTAS < B ? GRID_CTAS : B;
    afm_mma_kernel<<<grid, NTH, SMEM_TOTAL>>>(x, emb, lin, lb, W1, b1, w2, pwv, (float*)d_out, B);
}